// round 12
// baseline (speedup 1.0000x reference)
#include <cuda_runtime.h>
#include <math_constants.h>

// out = softmax(p1 @ p2^T * sqrt(N2)) @ p2 ; N1=N2=8192, D=128, fp32.
//
// Round 12: R11 pipeline fix. R11 prefetched only 4 float4/thread for a
// BN=64 tile that needs 8 (2048 float4 / 256 threads) -> rows 32..63 of skv
// were stale, rel_err 0.94. kvreg[8] now covers the full tile.
//   * KV tile it+1 LDG'd into 8 regs right after the tile-ready barrier,
//     committed to smem at the next tile top: LDG latency hidden behind a
//     full tile of compute. Barrier count unchanged vs R10.
//   * GEMM1 two j-passes (acc2[4][2]) keeps peak regs ~124 < 128 cap.
// Everything else identical to R10 (grid 296, split-KV x8 round-robin,
// BN=64, plain P + PACK2 GEMM2, deferred l, ex2.approx).

#define N1v 8192
#define N2v 8192
#define DD  128
#define BM  64
#define BN  64
#define NSPLIT 8
#define NKV_JOB (N2v / NSPLIT)         // 1024 rows per job
#define NT_JOB  (NKV_JOB / BN)         // 16 tiles per job
#define NJOBS   ((N1v / BM) * NSPLIT)  // 1024
#define GRID    296                    // 2 CTAs x 148 SMs
#define KVPAD 132
#define PPAD  68
#define NTHREADS 256
#define C2F 130.57784f                 // sqrt(8192) * log2(e)

// packed f32x2 ops (ptxas never auto-fuses these from C++)
#define FMA2(d, a, b) asm("fma.rn.f32x2 %0, %1, %2, %0;" : "+l"(d) : "l"(a), "l"(b))
#define MUL2(d, s)    asm("mul.rn.f32x2 %0, %0, %1;"     : "+l"(d) : "l"(s))
#define PACK2(d, x, y) asm("mov.b64 %0, {%1, %2};" : "=l"(d) : "f"(x), "f"(y))
#define UNPACK2(lo, hi, v) asm("mov.b64 {%0, %1}, %2;" : "=f"(lo), "=f"(hi) : "l"(v))

__device__ __forceinline__ float ex2(float x) {
    float r;
    asm("ex2.approx.ftz.f32 %0, %1;" : "=f"(r) : "f"(x));
    return r;
}

// ---- split-KV scratch (static device globals: no runtime allocation) ----
__device__ float g_opart[NSPLIT][N1v][DD];
__device__ float g_m[NSPLIT][N1v];
__device__ float g_l[NSPLIT][N1v];

__global__ __launch_bounds__(NTHREADS, 2)
void attn_fwd_kernel(const float* __restrict__ P1,
                     const float* __restrict__ P2)
{
    extern __shared__ float smem[];
    float* sq  = smem;                      // [BM][KVPAD]
    float* skv = sq  + BM * KVPAD;          // [BN][KVPAD]
    float* sp  = skv + BN * KVPAD;          // [BM][PPAD]

    const int t   = threadIdx.x;
    const int mr  = t >> 4;                 // 0..15 row-group id
    const int mc  = t & 15;                 // 0..15 lane within row-group
    const int r0  = mr * 4;                 // this thread's 4 score/output rows
    const int dcA = 4 * mc;                 // GEMM2 output cols {4mc..4mc+3}
    const int dcB = 64 + 4 * mc;
    const int ldrow = t >> 5;               // tile-load base row (0..7)
    const int ldc4  = t & 31;               // tile-load float4 column

    for (int job = blockIdx.x; job < NJOBS; job += GRID) {
        const int qt    = job >> 3;
        const int s     = job & (NSPLIT - 1);
        const int qbase = qt * BM;
        const int kv0   = s * NKV_JOB;

        // ---- load Q tile ----
        {
            const float4* src = (const float4*)(P1 + (size_t)qbase * DD);
            #pragma unroll
            for (int i = 0; i < 8; i++) {
                int idx = t + i * NTHREADS;
                int row = idx >> 5, c4 = idx & 31;
                *(float4*)&sq[row * KVPAD + c4 * 4] = src[idx];
            }
        }

        // ---- prefetch KV tile 0 of this job into registers (FULL tile: 8) ----
        float4 kvreg[8];
        {
            const float4* src = (const float4*)(P2 + (size_t)kv0 * DD);
            #pragma unroll
            for (int i = 0; i < 8; i++) kvreg[i] = src[t + i * NTHREADS];
        }

        // ---- softmax state + packed O accumulators ----
        float m_run[4], l_lane[4];
        unsigned long long o2[4][4];
        #pragma unroll
        for (int i = 0; i < 4; i++) {
            m_run[i] = -CUDART_INF_F;
            l_lane[i] = 0.f;
            #pragma unroll
            for (int d = 0; d < 4; d++) o2[i][d] = 0ull;
        }

        __syncthreads();   // sq ready; previous job fully done with smem

        for (int it = 0; it < NT_JOB; it++) {
            // ---- commit prefetched KV tile to smem (rows ldrow+8i, i=0..7) ----
            #pragma unroll
            for (int i = 0; i < 8; i++)
                *(float4*)&skv[(ldrow + i * 8) * KVPAD + ldc4 * 4] = kvreg[i];
            __syncthreads();   // skv ready

            // ---- prefetch next tile (consumed a full tile of compute later) ----
            if (it + 1 < NT_JOB) {
                const float4* src =
                    (const float4*)(P2 + (size_t)(kv0 + (it + 1) * BN) * DD);
                #pragma unroll
                for (int i = 0; i < 8; i++) kvreg[i] = src[t + i * NTHREADS];
            }

            // ---- GEMM1 in two j-passes: sv[i][j] = q[r0+i] . kv[mc+16j] ----
            float sv[4][4];
            #pragma unroll
            for (int h = 0; h < 2; h++) {
                unsigned long long acc2[4][2];
                #pragma unroll
                for (int i = 0; i < 4; i++) { acc2[i][0] = 0ull; acc2[i][1] = 0ull; }

                const float* b0p = &skv[(mc + 32 * h) * KVPAD];
                const float* b1p = &skv[(mc + 32 * h + 16) * KVPAD];
                #pragma unroll 2
                for (int k = 0; k < DD; k += 4) {
                    ulonglong2 B0 = *(const ulonglong2*)(b0p + k);
                    ulonglong2 B1 = *(const ulonglong2*)(b1p + k);
                    #pragma unroll
                    for (int i = 0; i < 4; i++) {
                        ulonglong2 A = *(const ulonglong2*)&sq[(r0 + i) * KVPAD + k];
                        FMA2(acc2[i][0], A.x, B0.x);
                        FMA2(acc2[i][0], A.y, B0.y);
                        FMA2(acc2[i][1], A.x, B1.x);
                        FMA2(acc2[i][1], A.y, B1.y);
                    }
                }
                #pragma unroll
                for (int i = 0; i < 4; i++) {
                    float lo, hi;
                    UNPACK2(lo, hi, acc2[i][0]); sv[i][2 * h]     = lo + hi;
                    UNPACK2(lo, hi, acc2[i][1]); sv[i][2 * h + 1] = lo + hi;
                }
            }

            // ---- online softmax: max across 16-lane group; l deferred ----
            #pragma unroll
            for (int i = 0; i < 4; i++) {
                float mloc = fmaxf(fmaxf(sv[i][0], sv[i][1]),
                                   fmaxf(sv[i][2], sv[i][3])) * C2F;
                #pragma unroll
                for (int off = 1; off < 16; off <<= 1)
                    mloc = fmaxf(mloc, __shfl_xor_sync(0xffffffffu, mloc, off));

                float mnew = fmaxf(m_run[i], mloc);
                float corr = ex2(m_run[i] - mnew);   // ex2(-inf)=0 first tile
                m_run[i] = mnew;

                float p0 = ex2(fmaf(sv[i][0], C2F, -mnew));
                float p1 = ex2(fmaf(sv[i][1], C2F, -mnew));
                float p2 = ex2(fmaf(sv[i][2], C2F, -mnew));
                float p3 = ex2(fmaf(sv[i][3], C2F, -mnew));
                sp[(r0 + i) * PPAD + mc]      = p0;
                sp[(r0 + i) * PPAD + mc + 16] = p1;
                sp[(r0 + i) * PPAD + mc + 32] = p2;
                sp[(r0 + i) * PPAD + mc + 48] = p3;
                l_lane[i] = fmaf(l_lane[i], corr, (p0 + p1) + (p2 + p3));

                unsigned long long corr2;
                PACK2(corr2, corr, corr);
                #pragma unroll
                for (int d = 0; d < 4; d++) MUL2(o2[i][d], corr2);
            }
            // P rows r0..r0+3 produced & consumed within this 16-lane group
            __syncwarp();

            // ---- GEMM2: o2[i][.] += P[r0+i][j] * kv[j][cols] ----
            #pragma unroll 1
            for (int jb4 = 0; jb4 < BN; jb4 += 4) {
                float4 P4[4];
                #pragma unroll
                for (int i = 0; i < 4; i++)
                    P4[i] = *(const float4*)&sp[(r0 + i) * PPAD + jb4];
                #pragma unroll
                for (int jj = 0; jj < 4; jj++) {
                    const float* vr = &skv[(jb4 + jj) * KVPAD];
                    ulonglong2 vA = *(const ulonglong2*)(vr + dcA);
                    ulonglong2 vB = *(const ulonglong2*)(vr + dcB);
                    #pragma unroll
                    for (int i = 0; i < 4; i++) {
                        float pv = ((const float*)&P4[i])[jj];
                        unsigned long long pp;
                        PACK2(pp, pv, pv);
                        FMA2(o2[i][0], pp, vA.x);
                        FMA2(o2[i][1], pp, vA.y);
                        FMA2(o2[i][2], pp, vB.x);
                        FMA2(o2[i][3], pp, vB.y);
                    }
                }
            }
            __syncthreads();   // all reads of skv done before next STS
        }

        // ---- finalize l: one butterfly over the 16-lane row group ----
        float l_run[4];
        #pragma unroll
        for (int i = 0; i < 4; i++) {
            float l = l_lane[i];
            #pragma unroll
            for (int off = 1; off < 16; off <<= 1)
                l += __shfl_xor_sync(0xffffffffu, l, off);
            l_run[i] = l;
        }

        // ---- epilogue: per-split normalized partial + (m,l) ----
        if (mc == 0) {
            #pragma unroll
            for (int i = 0; i < 4; i++) {
                g_m[s][qbase + r0 + i] = m_run[i];
                g_l[s][qbase + r0 + i] = l_run[i];
            }
        }
        #pragma unroll
        for (int i = 0; i < 4; i++) {
            float inv = 1.0f / l_run[i];
            float f[8];
            #pragma unroll
            for (int d = 0; d < 4; d++) {
                float lo, hi;
                UNPACK2(lo, hi, o2[i][d]);
                f[2 * d]     = lo * inv;
                f[2 * d + 1] = hi * inv;
            }
            float* dst = &g_opart[s][qbase + r0 + i][0];
            *(float4*)(dst + dcA) = make_float4(f[0], f[1], f[2], f[3]);
            *(float4*)(dst + dcB) = make_float4(f[4], f[5], f[6], f[7]);
        }
    }
}

// combine the NSPLIT KV splits:  out = sum_s w_s*o_s / sum_s w_s, w = l*2^(m-M)
__global__ void merge_kernel(float* __restrict__ out)
{
    int idx = blockIdx.x * blockDim.x + threadIdx.x;   // over 8192*128
    int row = idx >> 7;
    int col = idx & (DD - 1);

    float m[NSPLIT];
    float M = -CUDART_INF_F;
    #pragma unroll
    for (int s = 0; s < NSPLIT; s++) {
        m[s] = g_m[s][row];
        M = fmaxf(M, m[s]);
    }
    float wsum = 0.f, acc = 0.f;
    #pragma unroll
    for (int s = 0; s < NSPLIT; s++) {
        float w = g_l[s][row] * exp2f(m[s] - M);
        acc  = fmaf(w, g_opart[s][row][col], acc);
        wsum += w;
    }
    out[idx] = acc / wsum;
}

extern "C" void kernel_launch(void* const* d_in, const int* in_sizes, int n_in,
                              void* d_out, int out_size)
{
    const float* p1 = (const float*)d_in[0];
    const float* p2 = (const float*)d_in[1];
    float* out = (float*)d_out;

    const int smem_bytes = (BM * KVPAD + BN * KVPAD + BM * PPAD) * (int)sizeof(float);
    cudaFuncSetAttribute(attn_fwd_kernel,
                         cudaFuncAttributeMaxDynamicSharedMemorySize, smem_bytes);

    attn_fwd_kernel<<<GRID, NTHREADS, smem_bytes>>>(p1, p2);
    merge_kernel<<<(N1v * DD) / 256, 256>>>(out);
}

// round 13
// speedup vs baseline: 1.2958x; 1.2958x over previous
#include <cuda_runtime.h>
#include <math_constants.h>
#include <cstdint>

// out = softmax(p1 @ p2^T * sqrt(N2)) @ p2 ; N1=N2=8192, D=128, fp32.
//
// Round 13: R10 compute core (proven 729us) + cp.async double-buffered KV.
//   * kv prefetch via cp.async.cg -> NO register cost (R12's kvreg[8] spilled).
//   * skv stride 128 with 16B-chunk XOR swizzle (c ^= row&7): conflict
//     profile identical to padded-132, saves 4KB -> two KV buffers fit in
//     115712 B/CTA (2 CTAs/SM incl. driver reserve).
//   * ONE __syncthreads per tile (publishes tile it + retires buffer it+1).
//   * sp PPAD=64 (fits budget; only a 2-phase broadcast on P4 loads).
// Grid 296, split-KV x8 round-robin, BN=64, deferred l, ex2.approx unchanged.

#define N1v 8192
#define N2v 8192
#define DD  128
#define BM  64
#define BN  64
#define NSPLIT 8
#define NKV_JOB (N2v / NSPLIT)         // 1024 rows per job
#define NT_JOB  (NKV_JOB / BN)         // 16 tiles per job
#define NJOBS   ((N1v / BM) * NSPLIT)  // 1024
#define GRID    296                    // 2 CTAs x 148 SMs
#define SQPAD 132                      // sq row stride (floats), 16B-aligned rows
#define PPAD  64                       // sp row stride (floats)
#define NTHREADS 256
#define C2F 130.57784f                 // sqrt(8192) * log2(e)

// smem layout (bytes)
#define SQ_B    0
#define SKV_B   (BM * SQPAD * 4)               // 33792 ; 2 buffers x 32768 B
#define SP_B    (SKV_B + 2 * BN * 128 * 4)     // + 65536
#define SMEM_B  (SP_B + BM * PPAD * 4)         // 115712 total

// packed f32x2 ops (ptxas never auto-fuses these from C++)
#define FMA2(d, a, b) asm("fma.rn.f32x2 %0, %1, %2, %0;" : "+l"(d) : "l"(a), "l"(b))
#define MUL2(d, s)    asm("mul.rn.f32x2 %0, %0, %1;"     : "+l"(d) : "l"(s))
#define PACK2(d, x, y) asm("mov.b64 %0, {%1, %2};" : "=l"(d) : "f"(x), "f"(y))
#define UNPACK2(lo, hi, v) asm("mov.b64 {%0, %1}, %2;" : "=f"(lo), "=f"(hi) : "l"(v))

__device__ __forceinline__ float ex2(float x) {
    float r;
    asm("ex2.approx.ftz.f32 %0, %1;" : "=f"(r) : "f"(x));
    return r;
}
__device__ __forceinline__ uint32_t smem_u32(const void* p) {
    uint32_t a;
    asm("{ .reg .u64 t; cvta.to.shared.u64 t, %1; cvt.u32.u64 %0, t; }" : "=r"(a) : "l"(p));
    return a;
}
__device__ __forceinline__ void cp_async16(uint32_t dst, const void* src) {
    asm volatile("cp.async.cg.shared.global [%0], [%1], 16;" :: "r"(dst), "l"(src) : "memory");
}
#define CP_COMMIT() asm volatile("cp.async.commit_group;" ::: "memory")
#define CP_WAIT0()  asm volatile("cp.async.wait_group 0;" ::: "memory")

// ---- split-KV scratch (static device globals: no runtime allocation) ----
__device__ float g_opart[NSPLIT][N1v][DD];
__device__ float g_m[NSPLIT][N1v];
__device__ float g_l[NSPLIT][N1v];

__global__ __launch_bounds__(NTHREADS, 2)
void attn_fwd_kernel(const float* __restrict__ P1,
                     const float* __restrict__ P2)
{
    extern __shared__ float smem[];
    float* sq = (float*)((char*)smem + SQ_B);   // [BM][SQPAD]
    float* sp = (float*)((char*)smem + SP_B);   // [BM][PPAD]
    const uint32_t sbu = smem_u32(smem);

    const int t   = threadIdx.x;
    const int mr  = t >> 4;                 // 0..15 row-group id
    const int mc  = t & 15;                 // 0..15 lane within row-group
    const int r0  = mr * 4;                 // this thread's 4 score/output rows
    const int dcA = 4 * mc;                 // GEMM2 output col base (chunk mc)
    const int ldrow = t >> 5;               // tile-load base row (0..7)
    const int ldc4  = t & 31;               // tile-load 16B-chunk column
    // per-thread constant swizzled commit offset within a row
    const uint32_t swzc = (uint32_t)((ldc4 ^ ldrow) << 4);
    const int xr = (mc & 7) << 4;           // GEMM1 B swizzle term (row&7 == mc&7)

    for (int job = blockIdx.x; job < NJOBS; job += GRID) {
        const int qt    = job >> 3;
        const int s     = job & (NSPLIT - 1);
        const int qbase = qt * BM;
        const int kv0   = s * NKV_JOB;

        __syncthreads();   // previous job fully done with smem (sq/skv/sp)

        // ---- load Q tile (sync) ----
        {
            const float4* src = (const float4*)(P1 + (size_t)qbase * DD);
            #pragma unroll
            for (int i = 0; i < 8; i++) {
                int idx = t + i * NTHREADS;
                int row = idx >> 5, c4 = idx & 31;
                *(float4*)&sq[row * SQPAD + c4 * 4] = src[idx];
            }
        }

        // ---- cp.async KV tile 0 into buffer 0 (swizzled) ----
        {
            const float4* src = (const float4*)(P2 + (size_t)kv0 * DD);
            #pragma unroll
            for (int i = 0; i < 8; i++)
                cp_async16(sbu + SKV_B + (uint32_t)((ldrow + 8 * i) * 512) + swzc,
                           src + t + i * NTHREADS);
            CP_COMMIT();
        }

        // ---- softmax state + packed O accumulators ----
        float m_run[4], l_lane[4];
        unsigned long long o2[4][4];
        #pragma unroll
        for (int i = 0; i < 4; i++) {
            m_run[i] = -CUDART_INF_F;
            l_lane[i] = 0.f;
            #pragma unroll
            for (int d = 0; d < 4; d++) o2[i][d] = 0ull;
        }

        for (int it = 0; it < NT_JOB; it++) {
            CP_WAIT0();
            __syncthreads();   // tile it visible; buffer (it+1)&1 free; sq ready

            // ---- prefetch tile it+1 into the other buffer ----
            if (it + 1 < NT_JOB) {
                const float4* src =
                    (const float4*)(P2 + (size_t)(kv0 + (it + 1) * BN) * DD);
                uint32_t base = sbu + SKV_B + (uint32_t)(((it + 1) & 1) * 32768) + swzc;
                #pragma unroll
                for (int i = 0; i < 8; i++)
                    cp_async16(base + (uint32_t)((ldrow + 8 * i) * 512),
                               src + t + i * NTHREADS);
                CP_COMMIT();
            }

            const char* skvb = (const char*)smem + SKV_B + (it & 1) * 32768;

            // ---- GEMM1: acc2[i][j] = q[r0+i] . kv[mc+16j] (swizzled B) ----
            unsigned long long acc2[4][4];
            #pragma unroll
            for (int i = 0; i < 4; i++)
                #pragma unroll
                for (int j = 0; j < 4; j++) acc2[i][j] = 0ull;

            const char* b0 = skvb + mc * 512;
            const char* b1 = skvb + (mc + 16) * 512;
            const char* b2 = skvb + (mc + 32) * 512;
            const char* b3 = skvb + (mc + 48) * 512;

            #pragma unroll 2
            for (int k = 0; k < DD; k += 4) {
                int cs = (k << 2) ^ xr;        // ((k>>2)<<4) ^ ((mc&7)<<4)
                ulonglong2 B0 = *(const ulonglong2*)(b0 + cs);
                ulonglong2 B1 = *(const ulonglong2*)(b1 + cs);
                ulonglong2 B2 = *(const ulonglong2*)(b2 + cs);
                ulonglong2 B3 = *(const ulonglong2*)(b3 + cs);
                #pragma unroll
                for (int i = 0; i < 4; i++) {
                    ulonglong2 A = *(const ulonglong2*)&sq[(r0 + i) * SQPAD + k];
                    FMA2(acc2[i][0], A.x, B0.x);
                    FMA2(acc2[i][0], A.y, B0.y);
                    FMA2(acc2[i][1], A.x, B1.x);
                    FMA2(acc2[i][1], A.y, B1.y);
                    FMA2(acc2[i][2], A.x, B2.x);
                    FMA2(acc2[i][2], A.y, B2.y);
                    FMA2(acc2[i][3], A.x, B3.x);
                    FMA2(acc2[i][3], A.y, B3.y);
                }
            }

            // ---- online softmax: max across 16-lane group; l deferred ----
            #pragma unroll
            for (int i = 0; i < 4; i++) {
                float sv[4];
                #pragma unroll
                for (int j = 0; j < 4; j++) {
                    float lo, hi;
                    UNPACK2(lo, hi, acc2[i][j]);
                    sv[j] = lo + hi;
                }
                float mloc = fmaxf(fmaxf(sv[0], sv[1]), fmaxf(sv[2], sv[3])) * C2F;
                #pragma unroll
                for (int off = 1; off < 16; off <<= 1)
                    mloc = fmaxf(mloc, __shfl_xor_sync(0xffffffffu, mloc, off));

                float mnew = fmaxf(m_run[i], mloc);
                float corr = ex2(m_run[i] - mnew);   // ex2(-inf)=0 first tile
                m_run[i] = mnew;

                float p0 = ex2(fmaf(sv[0], C2F, -mnew));
                float p1 = ex2(fmaf(sv[1], C2F, -mnew));
                float p2 = ex2(fmaf(sv[2], C2F, -mnew));
                float p3 = ex2(fmaf(sv[3], C2F, -mnew));
                sp[(r0 + i) * PPAD + mc]      = p0;
                sp[(r0 + i) * PPAD + mc + 16] = p1;
                sp[(r0 + i) * PPAD + mc + 32] = p2;
                sp[(r0 + i) * PPAD + mc + 48] = p3;
                l_lane[i] = fmaf(l_lane[i], corr, (p0 + p1) + (p2 + p3));

                unsigned long long corr2;
                PACK2(corr2, corr, corr);
                #pragma unroll
                for (int d = 0; d < 4; d++) MUL2(o2[i][d], corr2);
            }
            // P rows r0..r0+3 produced & consumed within this 16-lane group
            __syncwarp();

            // ---- GEMM2: o2[i][.] += P[r0+i][j] * kv[j][cols] (swizzled V) ----
            #pragma unroll 1
            for (int jb4 = 0; jb4 < BN; jb4 += 4) {
                float4 P4[4];
                #pragma unroll
                for (int i = 0; i < 4; i++)
                    P4[i] = *(const float4*)&sp[(r0 + i) * PPAD + jb4];
                #pragma unroll
                for (int jj = 0; jj < 4; jj++) {
                    int row = jb4 + jj;
                    const char* vr = skvb + row * 512;
                    int o = (dcA << 2) ^ ((row & 7) << 4);  // ((mc^(row&7))<<4)
                    ulonglong2 vA = *(const ulonglong2*)(vr + o);
                    ulonglong2 vB = *(const ulonglong2*)(vr + 256 + o);
                    #pragma unroll
                    for (int i = 0; i < 4; i++) {
                        float pv = ((const float*)&P4[i])[jj];
                        unsigned long long pp;
                        PACK2(pp, pv, pv);
                        FMA2(o2[i][0], pp, vA.x);
                        FMA2(o2[i][1], pp, vA.y);
                        FMA2(o2[i][2], pp, vB.x);
                        FMA2(o2[i][3], pp, vB.y);
                    }
                }
            }
            // next tile's top barrier retires this buffer
        }

        // ---- finalize l: one butterfly over the 16-lane row group ----
        float l_run[4];
        #pragma unroll
        for (int i = 0; i < 4; i++) {
            float l = l_lane[i];
            #pragma unroll
            for (int off = 1; off < 16; off <<= 1)
                l += __shfl_xor_sync(0xffffffffu, l, off);
            l_run[i] = l;
        }

        // ---- epilogue: per-split normalized partial + (m,l) ----
        if (mc == 0) {
            #pragma unroll
            for (int i = 0; i < 4; i++) {
                g_m[s][qbase + r0 + i] = m_run[i];
                g_l[s][qbase + r0 + i] = l_run[i];
            }
        }
        #pragma unroll
        for (int i = 0; i < 4; i++) {
            float inv = 1.0f / l_run[i];
            float f[8];
            #pragma unroll
            for (int d = 0; d < 4; d++) {
                float lo, hi;
                UNPACK2(lo, hi, o2[i][d]);
                f[2 * d]     = lo * inv;
                f[2 * d + 1] = hi * inv;
            }
            float* dst = &g_opart[s][qbase + r0 + i][0];
            *(float4*)(dst + dcA)      = make_float4(f[0], f[1], f[2], f[3]);
            *(float4*)(dst + 64 + dcA) = make_float4(f[4], f[5], f[6], f[7]);
        }
    }
}

// combine the NSPLIT KV splits:  out = sum_s w_s*o_s / sum_s w_s, w = l*2^(m-M)
__global__ void merge_kernel(float* __restrict__ out)
{
    int idx = blockIdx.x * blockDim.x + threadIdx.x;   // over 8192*128
    int row = idx >> 7;
    int col = idx & (DD - 1);

    float m[NSPLIT];
    float M = -CUDART_INF_F;
    #pragma unroll
    for (int s = 0; s < NSPLIT; s++) {
        m[s] = g_m[s][row];
        M = fmaxf(M, m[s]);
    }
    float wsum = 0.f, acc = 0.f;
    #pragma unroll
    for (int s = 0; s < NSPLIT; s++) {
        float w = g_l[s][row] * exp2f(m[s] - M);
        acc  = fmaf(w, g_opart[s][row][col], acc);
        wsum += w;
    }
    out[idx] = acc / wsum;
}

extern "C" void kernel_launch(void* const* d_in, const int* in_sizes, int n_in,
                              void* d_out, int out_size)
{
    const float* p1 = (const float*)d_in[0];
    const float* p2 = (const float*)d_in[1];
    float* out = (float*)d_out;

    cudaFuncSetAttribute(attn_fwd_kernel,
                         cudaFuncAttributeMaxDynamicSharedMemorySize, SMEM_B);

    attn_fwd_kernel<<<GRID, NTHREADS, SMEM_B>>>(p1, p2);
    merge_kernel<<<(N1v * DD) / 256, 256>>>(out);
}

// round 14
// speedup vs baseline: 1.3371x; 1.0319x over previous
#include <cuda_runtime.h>
#include <math_constants.h>
#include <cuda_fp16.h>
#include <cstdint>

// out = softmax(p1 @ p2^T * sqrt(N2)) @ p2 ; N1=N2=8192, D=128, fp32.
//
// Round 14: GEMM1 -> legacy tensor core (mma.sync.m16n8k8 tf32, 3-way split:
// qh*kh + qh*kl + ql*kh). Q split once/job to smem (hi f32, lo fp16); K
// hi/lo built on the fly in registers from the raw KV tile. 8 warps =
// 4 row-blocks x 2 col-halves; cross-half row max/sum via smem. GEMM2 stays
// f32x2 CUDA-core (R13 core). Grid 296, split-KV x8, merge kernel unchanged.

#define N1v 8192
#define N2v 8192
#define DD  128
#define BM  64
#define BN  64
#define NSPLIT 8
#define NKV_JOB (N2v / NSPLIT)
#define NT_JOB  (NKV_JOB / BN)         // 16
#define NJOBS   ((N1v / BM) * NSPLIT)  // 1024
#define GRID    296
#define STR 132                        // row stride (elems) for sqh/sql/skv
#define PPAD 68
#define NTHREADS 256
#define C2F 130.57784f                 // sqrt(8192) * log2(e)

// smem layout (bytes)
#define SQH_B  0
#define SQL_B  (SQH_B + BM * STR * 4)      // 33792
#define SKV_B  (SQL_B + BM * STR * 2)      // +16896 = 50688
#define SP_B   (SKV_B + BN * STR * 4)      // +33792 = 84480
#define PMX_B  (SP_B + BM * PPAD * 4)      // +17408 = 101888
#define SCR_B  (PMX_B + 2 * 64 * 4)        // +512   = 102400
#define LH_B   (SCR_B + 64 * 4)            // +256   = 102656
#define SMEM_B (LH_B + 64 * 4)             // 102912

#define FMA2(d, a, b) asm("fma.rn.f32x2 %0, %1, %2, %0;" : "+l"(d) : "l"(a), "l"(b))
#define MUL2(d, s)    asm("mul.rn.f32x2 %0, %0, %1;"     : "+l"(d) : "l"(s))
#define PACK2(d, x, y) asm("mov.b64 %0, {%1, %2};" : "=l"(d) : "f"(x), "f"(y))
#define UNPACK2(lo, hi, v) asm("mov.b64 {%0, %1}, %2;" : "=f"(lo), "=f"(hi) : "l"(v))

#define MMA_TF32(d, a0, a1, a2, a3, b0, b1) \
    asm volatile("mma.sync.aligned.m16n8k8.row.col.f32.tf32.tf32.f32 " \
                 "{%0,%1,%2,%3},{%4,%5,%6,%7},{%8,%9},{%0,%1,%2,%3};" \
                 : "+f"((d)[0]), "+f"((d)[1]), "+f"((d)[2]), "+f"((d)[3]) \
                 : "r"(a0), "r"(a1), "r"(a2), "r"(a3), "r"(b0), "r"(b1))

__device__ __forceinline__ float ex2(float x) {
    float r;
    asm("ex2.approx.ftz.f32 %0, %1;" : "=f"(r) : "f"(x));
    return r;
}
__device__ __forceinline__ uint32_t tf32b(float x) {
    uint32_t r;
    asm("cvt.rna.tf32.f32 %0, %1;" : "=r"(r) : "f"(x));
    return r;
}

__device__ float g_opart[NSPLIT][N1v][DD];
__device__ float g_m[NSPLIT][N1v];
__device__ float g_l[NSPLIT][N1v];

__global__ __launch_bounds__(NTHREADS, 2)
void attn_fwd_kernel(const float* __restrict__ P1,
                     const float* __restrict__ P2)
{
    extern __shared__ char smem[];
    float*  sqh  = (float*)(smem + SQH_B);
    __half* sql  = (__half*)(smem + SQL_B);
    float*  skv  = (float*)(smem + SKV_B);
    float*  sp   = (float*)(smem + SP_B);
    float*  pmax = (float*)(smem + PMX_B);
    float*  scor = (float*)(smem + SCR_B);
    float*  lh   = (float*)(smem + LH_B);

    const int t    = threadIdx.x;
    const int wid  = t >> 5, lane = t & 31;
    const int gid  = lane >> 2, tid = lane & 3;
    const int wr   = 16 * (wid & 3);        // mma row-block base
    const int wc   = 32 * (wid >> 2);       // mma col-half base (0/32)
    const int ph   = wid >> 2;              // col-half id
    const int rA   = wr + gid, rB = rA + 8; // this lane's two S rows
    // GEMM2 layout (R13):
    const int mr  = t >> 4, mc = t & 15;
    const int r0  = mr * 4;
    const int dcA = 4 * mc, dcB = 64 + 4 * mc;

    for (int job = blockIdx.x; job < NJOBS; job += GRID) {
        const int qt    = job >> 3;
        const int s     = job & (NSPLIT - 1);
        const int qbase = qt * BM;
        const int kv0   = s * NKV_JOB;

        __syncthreads();   // previous job fully done with smem

        // ---- load + tf32-split Q tile (hi f32, lo fp16) ----
        {
            const float4* src = (const float4*)(P1 + (size_t)qbase * DD);
            #pragma unroll
            for (int i = 0; i < 8; i++) {
                int idx = t + i * NTHREADS;
                int row = idx >> 5, c4 = (idx & 31) * 4;
                float4 v = src[idx];
                float hx = __uint_as_float(tf32b(v.x));
                float hy = __uint_as_float(tf32b(v.y));
                float hz = __uint_as_float(tf32b(v.z));
                float hw = __uint_as_float(tf32b(v.w));
                float* qh = &sqh[row * STR + c4];
                qh[0] = hx; qh[1] = hy; qh[2] = hz; qh[3] = hw;
                __half2* ql = (__half2*)&sql[row * STR + c4];
                ql[0] = __floats2half2_rn(v.x - hx, v.y - hy);
                ql[1] = __floats2half2_rn(v.z - hz, v.w - hw);
            }
        }

        float m0 = -CUDART_INF_F, m1 = -CUDART_INF_F, l0 = 0.f, l1 = 0.f;
        unsigned long long o2[4][4];
        #pragma unroll
        for (int i = 0; i < 4; i++)
            #pragma unroll
            for (int d = 0; d < 4; d++) o2[i][d] = 0ull;

        for (int it = 0; it < NT_JOB; it++) {
            // ---- load raw KV tile ----
            {
                const float4* src =
                    (const float4*)(P2 + (size_t)(kv0 + it * BN) * DD);
                #pragma unroll
                for (int i = 0; i < 8; i++) {
                    int idx = t + i * NTHREADS;
                    int row = idx >> 5, c4 = (idx & 31) * 4;
                    *(float4*)&skv[row * STR + c4] = src[idx];
                }
            }
            __syncthreads();   // skv (and sq on it==0) visible

            // ---- GEMM1 on tensor pipe: S = qh*kh + qh*kl + ql*kh ----
            float D[4][4];
            #pragma unroll
            for (int nb = 0; nb < 4; nb++)
                #pragma unroll
                for (int c = 0; c < 4; c++) D[nb][c] = 0.f;

            const float*  qhp = &sqh[rA * STR + tid];
            const __half* qlp = &sql[rA * STR + tid];
            #pragma unroll 4
            for (int ks = 0; ks < 16; ks++) {
                const int k0 = ks * 8;
                uint32_t a0 = __float_as_uint(qhp[k0]);
                uint32_t a1 = __float_as_uint(qhp[k0 + 8 * STR]);
                uint32_t a2 = __float_as_uint(qhp[k0 + 4]);
                uint32_t a3 = __float_as_uint(qhp[k0 + 8 * STR + 4]);
                uint32_t e0 = __float_as_uint(__half2float(qlp[k0]));
                uint32_t e1 = __float_as_uint(__half2float(qlp[k0 + 8 * STR]));
                uint32_t e2 = __float_as_uint(__half2float(qlp[k0 + 4]));
                uint32_t e3 = __float_as_uint(__half2float(qlp[k0 + 8 * STR + 4]));
                #pragma unroll
                for (int nb = 0; nb < 4; nb++) {
                    const float* bp = &skv[(wc + nb * 8 + gid) * STR + k0 + tid];
                    float br0 = bp[0], br1 = bp[4];
                    uint32_t bh0 = tf32b(br0);
                    uint32_t bh1 = tf32b(br1);
                    uint32_t bl0 = tf32b(br0 - __uint_as_float(bh0));
                    uint32_t bl1 = tf32b(br1 - __uint_as_float(bh1));
                    MMA_TF32(D[nb], a0, a1, a2, a3, bh0, bh1);
                    MMA_TF32(D[nb], a0, a1, a2, a3, bl0, bl1);
                    MMA_TF32(D[nb], e0, e1, e2, e3, bh0, bh1);
                }
            }

            // ---- softmax: cross-half max via smem ----
            float mx0 = fmaxf(fmaxf(D[0][0], D[0][1]), fmaxf(D[1][0], D[1][1]));
            mx0 = fmaxf(mx0, fmaxf(fmaxf(D[2][0], D[2][1]), fmaxf(D[3][0], D[3][1])));
            float mx1 = fmaxf(fmaxf(D[0][2], D[0][3]), fmaxf(D[1][2], D[1][3]));
            mx1 = fmaxf(mx1, fmaxf(fmaxf(D[2][2], D[2][3]), fmaxf(D[3][2], D[3][3])));
            mx0 *= C2F; mx1 *= C2F;
            #pragma unroll
            for (int off = 1; off < 4; off <<= 1) {
                mx0 = fmaxf(mx0, __shfl_xor_sync(0xffffffffu, mx0, off));
                mx1 = fmaxf(mx1, __shfl_xor_sync(0xffffffffu, mx1, off));
            }
            if (tid == 0) {
                pmax[ph * 64 + rA] = mx0;
                pmax[ph * 64 + rB] = mx1;
            }
            __syncthreads();
            float mn0 = fmaxf(m0, fmaxf(mx0, pmax[(1 - ph) * 64 + rA]));
            float mn1 = fmaxf(m1, fmaxf(mx1, pmax[(1 - ph) * 64 + rB]));
            float cr0 = ex2(m0 - mn0), cr1 = ex2(m1 - mn1);
            m0 = mn0; m1 = mn1;

            float ps0 = 0.f, ps1 = 0.f;
            #pragma unroll
            for (int nb = 0; nb < 4; nb++) {
                float p00 = ex2(fmaf(D[nb][0], C2F, -mn0));
                float p01 = ex2(fmaf(D[nb][1], C2F, -mn0));
                float p10 = ex2(fmaf(D[nb][2], C2F, -mn1));
                float p11 = ex2(fmaf(D[nb][3], C2F, -mn1));
                int cc = wc + nb * 8 + 2 * tid;
                *(float2*)&sp[rA * PPAD + cc] = make_float2(p00, p01);
                *(float2*)&sp[rB * PPAD + cc] = make_float2(p10, p11);
                ps0 += p00 + p01; ps1 += p10 + p11;
            }
            l0 = fmaf(l0, cr0, ps0);
            l1 = fmaf(l1, cr1, ps1);
            if (ph == 0 && tid == 0) { scor[rA] = cr0; scor[rB] = cr1; }
            __syncthreads();   // P + corr visible

            // ---- GEMM2 (f32x2): o2 *= corr; o2 += P @ V ----
            #pragma unroll
            for (int i = 0; i < 4; i++) {
                float c = scor[r0 + i];
                unsigned long long c2;
                PACK2(c2, c, c);
                #pragma unroll
                for (int d = 0; d < 4; d++) MUL2(o2[i][d], c2);
            }
            #pragma unroll 1
            for (int jb4 = 0; jb4 < BN; jb4 += 4) {
                float4 P4[4];
                #pragma unroll
                for (int i = 0; i < 4; i++)
                    P4[i] = *(const float4*)&sp[(r0 + i) * PPAD + jb4];
                #pragma unroll
                for (int jj = 0; jj < 4; jj++) {
                    const float* vr = &skv[(jb4 + jj) * STR];
                    ulonglong2 vA = *(const ulonglong2*)(vr + dcA);
                    ulonglong2 vB = *(const ulonglong2*)(vr + dcB);
                    #pragma unroll
                    for (int i = 0; i < 4; i++) {
                        float pv = ((const float*)&P4[i])[jj];
                        unsigned long long pp;
                        PACK2(pp, pv, pv);
                        FMA2(o2[i][0], pp, vA.x);
                        FMA2(o2[i][1], pp, vA.y);
                        FMA2(o2[i][2], pp, vB.x);
                        FMA2(o2[i][3], pp, vB.y);
                    }
                }
            }
            __syncthreads();   // protect skv/sp/pmax/scor for next tile
        }

        // ---- finalize l: 4-lane sum, then cross-half combine ----
        #pragma unroll
        for (int off = 1; off < 4; off <<= 1) {
            l0 += __shfl_xor_sync(0xffffffffu, l0, off);
            l1 += __shfl_xor_sync(0xffffffffu, l1, off);
        }
        if (ph == 0 && tid == 0) { lh[rA] = l0; lh[rB] = l1; }
        __syncthreads();
        if (ph == 1 && tid == 0) {
            float L0 = l0 + lh[rA], L1 = l1 + lh[rB];
            g_m[s][qbase + rA] = m0; g_l[s][qbase + rA] = L0;
            g_m[s][qbase + rB] = m1; g_l[s][qbase + rB] = L1;
            scor[rA] = 1.0f / L0;    scor[rB] = 1.0f / L1;
        }
        __syncthreads();

        // ---- epilogue (GEMM2 layout) ----
        #pragma unroll
        for (int i = 0; i < 4; i++) {
            float inv = scor[r0 + i];
            float f[8];
            #pragma unroll
            for (int d = 0; d < 4; d++) {
                float lo, hi;
                UNPACK2(lo, hi, o2[i][d]);
                f[2 * d] = lo * inv; f[2 * d + 1] = hi * inv;
            }
            float* dst = &g_opart[s][qbase + r0 + i][0];
            *(float4*)(dst + dcA) = make_float4(f[0], f[1], f[2], f[3]);
            *(float4*)(dst + dcB) = make_float4(f[4], f[5], f[6], f[7]);
        }
    }
}

__global__ void merge_kernel(float* __restrict__ out)
{
    int idx = blockIdx.x * blockDim.x + threadIdx.x;
    int row = idx >> 7;
    int col = idx & (DD - 1);
    float m[NSPLIT];
    float M = -CUDART_INF_F;
    #pragma unroll
    for (int s = 0; s < NSPLIT; s++) { m[s] = g_m[s][row]; M = fmaxf(M, m[s]); }
    float wsum = 0.f, acc = 0.f;
    #pragma unroll
    for (int s = 0; s < NSPLIT; s++) {
        float w = g_l[s][row] * exp2f(m[s] - M);
        acc  = fmaf(w, g_opart[s][row][col], acc);
        wsum += w;
    }
    out[idx] = acc / wsum;
}

extern "C" void kernel_launch(void* const* d_in, const int* in_sizes, int n_in,
                              void* d_out, int out_size)
{
    const float* p1 = (const float*)d_in[0];
    const float* p2 = (const float*)d_in[1];
    float* out = (float*)d_out;

    cudaFuncSetAttribute(attn_fwd_kernel,
                         cudaFuncAttributeMaxDynamicSharedMemorySize, SMEM_B);
    attn_fwd_kernel<<<GRID, NTHREADS, SMEM_B>>>(p1, p2);
    merge_kernel<<<(N1v * DD) / 256, 256>>>(out);
}

// round 15
// speedup vs baseline: 2.0487x; 1.5322x over previous
#include <cuda_runtime.h>
#include <math_constants.h>
#include <cuda_fp16.h>
#include <cstdint>

// out = softmax(p1 @ p2^T * sqrt(N2)) @ p2 ; N1=N2=8192, D=128, fp32.
//
// Round 15: BOTH GEMMs on mma.sync.m16n8k8.tf32.
//  * GEMM1: 3-way truncation split (hi = raw f32, HW ignores low 13 bits;
//    lo = v - (v & 0xFFFFE000): LOP3+FSUB instead of cvt.rna chains).
//    Q-hi raw + Q-lo fp16 precomputed once/job in fragment-paired order.
//  * GEMM2: single MMA set. P rounded to tf32 at softmax (l accumulated from
//    rounded P -> unbiased weighted mean); V rounded per-fragment.
//  * O accumulators live in MMA D fragments; corr applied in-register.
// Grid 296, split-KV x8 round-robin, merge kernel unchanged.

#define N1v 8192
#define N2v 8192
#define DD  128
#define BM  64
#define BN  64
#define NSPLIT 8
#define NKV_JOB (N2v / NSPLIT)
#define NT_JOB  (NKV_JOB / BN)         // 16
#define NJOBS   ((N1v / BM) * NSPLIT)  // 1024
#define GRID    296
#define STR  132                       // f32 row stride (sqh, skv)
#define SQLS 144                       // fp16 row stride (sql)
#define PPAD 68                        // sp row stride
#define NTHREADS 256
#define C2F 130.57784f                 // sqrt(8192) * log2(e)

// smem layout (bytes)
#define SQH_B 0
#define SQL_B (SQH_B + BM * STR * 4)        // 33792
#define SKV_B (SQL_B + BM * SQLS * 2)       // +18432 = 52224
#define SP_B  (SKV_B + BN * STR * 4)        // +33792 = 86016
#define PMX_B (SP_B + BM * PPAD * 4)        // +17408 = 103424
#define LH_B  (PMX_B + 2 * 64 * 4)          // +512
#define SMEM_B (LH_B + 2 * 64 * 4)          // 104448 total

#define MMA_TF32(d, a0, a1, a2, a3, b0, b1) \
    asm volatile("mma.sync.aligned.m16n8k8.row.col.f32.tf32.tf32.f32 " \
                 "{%0,%1,%2,%3},{%4,%5,%6,%7},{%8,%9},{%0,%1,%2,%3};" \
                 : "+f"((d)[0]), "+f"((d)[1]), "+f"((d)[2]), "+f"((d)[3]) \
                 : "r"(a0), "r"(a1), "r"(a2), "r"(a3), "r"(b0), "r"(b1))

__device__ __forceinline__ float ex2(float x) {
    float r;
    asm("ex2.approx.ftz.f32 %0, %1;" : "=f"(r) : "f"(x));
    return r;
}
__device__ __forceinline__ uint32_t tf32rna(float x) {   // rounded tf32 bits
    uint32_t r;
    asm("cvt.rna.tf32.f32 %0, %1;" : "=r"(r) : "f"(x));
    return r;
}
__device__ __forceinline__ float trunct(float x) {       // tf32 truncation
    return __uint_as_float(__float_as_uint(x) & 0xFFFFE000u);
}
#define F2U(x) __float_as_uint(x)

__device__ float g_opart[NSPLIT][N1v][DD];
__device__ float g_m[NSPLIT][N1v];
__device__ float g_l[NSPLIT][N1v];

__global__ __launch_bounds__(NTHREADS, 2)
void attn_fwd_kernel(const float* __restrict__ P1,
                     const float* __restrict__ P2)
{
    extern __shared__ char smem[];
    float*  sqh  = (float*)(smem + SQH_B);
    __half* sql  = (__half*)(smem + SQL_B);
    float*  skv  = (float*)(smem + SKV_B);
    float*  sp   = (float*)(smem + SP_B);
    float*  pmax = (float*)(smem + PMX_B);
    float*  lh   = (float*)(smem + LH_B);

    const int t    = threadIdx.x;
    const int wid  = t >> 5, lane = t & 31;
    const int gid  = lane >> 2, tid = lane & 3;
    const int wr   = 16 * (wid & 3);        // m-block base (rows)
    const int ph   = wid >> 2;              // col-half id (0/1)
    const int wc   = 32 * ph;               // GEMM1 n-half base (S cols)
    const int wc2  = 64 * ph;               // GEMM2 n-half base (O cols)
    const int rA   = wr + gid, rB = rA + 8;

    for (int job = blockIdx.x; job < NJOBS; job += GRID) {
        const int qt    = job >> 3;
        const int s     = job & (NSPLIT - 1);
        const int qbase = qt * BM;
        const int kv0   = s * NKV_JOB;

        __syncthreads();   // previous job fully done with smem

        // ---- Q setup: raw-hi (fragment-paired) + fp16 lo (paired) ----
        {
            const float4* qsrc = (const float4*)(P1 + (size_t)qbase * DD);
            #pragma unroll
            for (int i = 0; i < 4; i++) {
                int cnk = t + i * NTHREADS;      // 0..1023 (8-float chunks)
                int row = cnk >> 4, ch = cnk & 15;
                float4 v0 = qsrc[row * 32 + ch * 2];
                float4 v1 = qsrc[row * 32 + ch * 2 + 1];
                float q[8] = {v0.x, v0.y, v0.z, v0.w, v1.x, v1.y, v1.z, v1.w};
                float2* dh = (float2*)&sqh[row * STR + ch * 8];
                __half2* dl = (__half2*)&sql[row * SQLS + ch * 8];
                #pragma unroll
                for (int j = 0; j < 4; j++) {
                    dh[j] = make_float2(q[j], q[j + 4]);   // (k, k+4) pair
                    dl[j] = __floats2half2_rn(q[j] - trunct(q[j]),
                                              q[j + 4] - trunct(q[j + 4]));
                }
            }
        }

        float m0 = -CUDART_INF_F, m1 = -CUDART_INF_F, l0 = 0.f, l1 = 0.f;
        float O[8][4];                       // O fragments: 8 n-blocks x 4
        #pragma unroll
        for (int nb = 0; nb < 8; nb++)
            #pragma unroll
            for (int c = 0; c < 4; c++) O[nb][c] = 0.f;

        for (int it = 0; it < NT_JOB; it++) {
            // ---- load raw KV tile ----
            {
                const float4* src =
                    (const float4*)(P2 + (size_t)(kv0 + it * BN) * DD);
                #pragma unroll
                for (int i = 0; i < 8; i++) {
                    int idx = t + i * NTHREADS;
                    int row = idx >> 5, c4 = (idx & 31) * 4;
                    *(float4*)&skv[row * STR + c4] = src[idx];
                }
            }
            __syncthreads();

            // ---- GEMM1: S = qh*kh + qh*kl + ql*kh (truncation split) ----
            float D[4][4];
            #pragma unroll
            for (int nb = 0; nb < 4; nb++)
                #pragma unroll
                for (int c = 0; c < 4; c++) D[nb][c] = 0.f;

            #pragma unroll 4
            for (int ks = 0; ks < 16; ks++) {
                const int k0 = ks * 8;
                float2 qa = *(const float2*)&sqh[rA * STR + k0 + 2 * tid];
                float2 qb = *(const float2*)&sqh[rB * STR + k0 + 2 * tid];
                float2 ea = __half22float2(
                    *(const __half2*)&sql[rA * SQLS + k0 + 2 * tid]);
                float2 eb = __half22float2(
                    *(const __half2*)&sql[rB * SQLS + k0 + 2 * tid]);
                uint32_t a0 = F2U(qa.x), a2 = F2U(qa.y);
                uint32_t a1 = F2U(qb.x), a3 = F2U(qb.y);
                uint32_t e0 = F2U(ea.x), e2 = F2U(ea.y);
                uint32_t e1 = F2U(eb.x), e3 = F2U(eb.y);
                #pragma unroll
                for (int nb = 0; nb < 4; nb++) {
                    const float* bp = &skv[(wc + nb * 8 + gid) * STR + k0 + tid];
                    float bv0 = bp[0], bv1 = bp[4];
                    uint32_t bh0 = F2U(bv0), bh1 = F2U(bv1);        // raw hi
                    uint32_t bl0 = F2U(bv0 - trunct(bv0));          // lo
                    uint32_t bl1 = F2U(bv1 - trunct(bv1));
                    MMA_TF32(D[nb], a0, a1, a2, a3, bh0, bh1);
                    MMA_TF32(D[nb], a0, a1, a2, a3, bl0, bl1);
                    MMA_TF32(D[nb], e0, e1, e2, e3, bh0, bh1);
                }
            }

            // ---- softmax (cross-half max via smem) ----
            float mx0 = fmaxf(fmaxf(D[0][0], D[0][1]), fmaxf(D[1][0], D[1][1]));
            mx0 = fmaxf(mx0, fmaxf(fmaxf(D[2][0], D[2][1]), fmaxf(D[3][0], D[3][1])));
            float mx1 = fmaxf(fmaxf(D[0][2], D[0][3]), fmaxf(D[1][2], D[1][3]));
            mx1 = fmaxf(mx1, fmaxf(fmaxf(D[2][2], D[2][3]), fmaxf(D[3][2], D[3][3])));
            mx0 *= C2F; mx1 *= C2F;
            #pragma unroll
            for (int off = 1; off < 4; off <<= 1) {
                mx0 = fmaxf(mx0, __shfl_xor_sync(0xffffffffu, mx0, off));
                mx1 = fmaxf(mx1, __shfl_xor_sync(0xffffffffu, mx1, off));
            }
            if (tid == 0) {
                pmax[ph * 64 + rA] = mx0;
                pmax[ph * 64 + rB] = mx1;
            }
            __syncthreads();
            float mn0 = fmaxf(m0, fmaxf(mx0, pmax[(1 - ph) * 64 + rA]));
            float mn1 = fmaxf(m1, fmaxf(mx1, pmax[(1 - ph) * 64 + rB]));
            float cr0 = ex2(m0 - mn0), cr1 = ex2(m1 - mn1);
            m0 = mn0; m1 = mn1;

            float ps0 = 0.f, ps1 = 0.f;
            #pragma unroll
            for (int nb = 0; nb < 4; nb++) {
                // round P to tf32; accumulate l from ROUNDED values
                float p00 = __uint_as_float(tf32rna(ex2(fmaf(D[nb][0], C2F, -mn0))));
                float p01 = __uint_as_float(tf32rna(ex2(fmaf(D[nb][1], C2F, -mn0))));
                float p10 = __uint_as_float(tf32rna(ex2(fmaf(D[nb][2], C2F, -mn1))));
                float p11 = __uint_as_float(tf32rna(ex2(fmaf(D[nb][3], C2F, -mn1))));
                int cc = wc + nb * 8 + 2 * tid;
                *(float2*)&sp[rA * PPAD + cc] = make_float2(p00, p01);
                *(float2*)&sp[rB * PPAD + cc] = make_float2(p10, p11);
                ps0 += p00 + p01; ps1 += p10 + p11;
            }
            l0 = fmaf(l0, cr0, ps0);
            l1 = fmaf(l1, cr1, ps1);
            __syncthreads();   // sp visible to all warps

            // ---- O *= corr (in-register; this warp's rows) ----
            #pragma unroll
            for (int nb = 0; nb < 8; nb++) {
                O[nb][0] *= cr0; O[nb][1] *= cr0;
                O[nb][2] *= cr1; O[nb][3] *= cr1;
            }

            // ---- GEMM2 on tensor: O += P~ @ V~ (single MMA set) ----
            #pragma unroll
            for (int ks = 0; ks < 8; ks++) {
                const int k0 = ks * 8;
                const float* pr = &sp[(wr + gid) * PPAD + k0 + tid];
                uint32_t a0 = F2U(pr[0]);
                uint32_t a1 = F2U(pr[8 * PPAD]);
                uint32_t a2 = F2U(pr[4]);
                uint32_t a3 = F2U(pr[8 * PPAD + 4]);
                #pragma unroll
                for (int nb = 0; nb < 8; nb++) {
                    const float* vp = &skv[(k0 + tid) * STR + wc2 + nb * 8 + gid];
                    uint32_t b0 = tf32rna(vp[0]);
                    uint32_t b1 = tf32rna(vp[4 * STR]);
                    MMA_TF32(O[nb], a0, a1, a2, a3, b0, b1);
                }
            }
            __syncthreads();   // skv/sp reads done before next tile load
        }

        // ---- finalize l: tid-group reduce, cross-half combine ----
        #pragma unroll
        for (int off = 1; off < 4; off <<= 1) {
            l0 += __shfl_xor_sync(0xffffffffu, l0, off);
            l1 += __shfl_xor_sync(0xffffffffu, l1, off);
        }
        if (tid == 0) {
            lh[ph * 64 + rA] = l0;
            lh[ph * 64 + rB] = l1;
        }
        __syncthreads();
        float L0 = lh[rA] + lh[64 + rA];
        float L1 = lh[rB] + lh[64 + rB];
        float inv0 = 1.0f / L0, inv1 = 1.0f / L1;
        if (ph == 0 && tid == 0) {
            g_m[s][qbase + rA] = m0; g_l[s][qbase + rA] = L0;
            g_m[s][qbase + rB] = m1; g_l[s][qbase + rB] = L1;
        }

        // ---- epilogue: normalized partial O from fragments ----
        {
            float* dstA = &g_opart[s][qbase + rA][wc2 + 2 * tid];
            float* dstB = &g_opart[s][qbase + rB][wc2 + 2 * tid];
            #pragma unroll
            for (int nb = 0; nb < 8; nb++) {
                *(float2*)(dstA + nb * 8) =
                    make_float2(O[nb][0] * inv0, O[nb][1] * inv0);
                *(float2*)(dstB + nb * 8) =
                    make_float2(O[nb][2] * inv1, O[nb][3] * inv1);
            }
        }
    }
}

// combine the NSPLIT KV splits:  out = sum_s w_s*o_s / sum_s w_s, w = l*2^(m-M)
__global__ void merge_kernel(float* __restrict__ out)
{
    int idx = blockIdx.x * blockDim.x + threadIdx.x;
    int row = idx >> 7;
    int col = idx & (DD - 1);
    float m[NSPLIT];
    float M = -CUDART_INF_F;
    #pragma unroll
    for (int s = 0; s < NSPLIT; s++) { m[s] = g_m[s][row]; M = fmaxf(M, m[s]); }
    float wsum = 0.f, acc = 0.f;
    #pragma unroll
    for (int s = 0; s < NSPLIT; s++) {
        float w = g_l[s][row] * exp2f(m[s] - M);
        acc  = fmaf(w, g_opart[s][row][col], acc);
        wsum += w;
    }
    out[idx] = acc / wsum;
}

extern "C" void kernel_launch(void* const* d_in, const int* in_sizes, int n_in,
                              void* d_out, int out_size)
{
    const float* p1 = (const float*)d_in[0];
    const float* p2 = (const float*)d_in[1];
    float* out = (float*)d_out;

    cudaFuncSetAttribute(attn_fwd_kernel,
                         cudaFuncAttributeMaxDynamicSharedMemorySize, SMEM_B);
    attn_fwd_kernel<<<GRID, NTHREADS, SMEM_B>>>(p1, p2);
    merge_kernel<<<(N1v * DD) / 256, 256>>>(out);
}

// round 16
// speedup vs baseline: 2.3344x; 1.1395x over previous
#include <cuda_runtime.h>
#include <math_constants.h>
#include <cuda_fp16.h>
#include <cstdint>

// out = softmax(p1 @ p2^T * sqrt(N2)) @ p2 ; N1=N2=8192, D=128, fp32.
//
// Round 16: operand-feeding diet on the R15 HMMA kernel.
//  * GEMM2 -> mma.m16n8k16.f16 (fp32 accum). V converted to fp16 at tile
//    load (sv16 [k][d]); B-frags via ldmatrix.x4.trans (16/tile vs 128
//    scalar LDS + 64 cvt). P stored fp16; l summed from the rounded P.
//  * GEMM1 K stored fragment-paired float2 (d, d+4) -> B-hi is one LDS.64;
//    lo built in-register from the same pair (raw hi: HW truncates tf32).
//  * raw skv removed; smem 110KB/CTA, still 2 CTAs/SM.
// Grid 296, split-KV x8 round-robin, merge kernel unchanged.

#define N1v 8192
#define N2v 8192
#define DD  128
#define BM  64
#define BN  64
#define NSPLIT 8
#define NKV_JOB (N2v / NSPLIT)
#define NT_JOB  (NKV_JOB / BN)         // 16
#define NJOBS   ((N1v / BM) * NSPLIT)  // 1024
#define GRID    296
#define QHS 132                        // sqh row stride (floats)
#define QLS 136                        // sql row stride (halves)
#define KPS 132                        // khp row stride (floats)
#define VS  136                        // sv16 row stride (halves) = 272B
#define PS  72                         // sp16 row stride (halves)
#define NTHREADS 256
#define C2F 130.57784f                 // sqrt(8192) * log2(e)

// smem layout (bytes)
#define SQH_B 0
#define SQL_B (SQH_B + BM * QHS * 4)        // 33792
#define KHP_B (SQL_B + BM * QLS * 2)        // 51200
#define SV_B  (KHP_B + BN * KPS * 4)        // 84992
#define SP_B  (SV_B + BN * VS * 2)          // 102400
#define PMX_B (SP_B + BM * PS * 2)          // 111616
#define LH_B  (PMX_B + 2 * 64 * 4)          // 112128
#define SMEM_B (LH_B + 2 * 64 * 4)          // 112640

#define MMA_TF32(d, a0, a1, a2, a3, b0, b1) \
    asm volatile("mma.sync.aligned.m16n8k8.row.col.f32.tf32.tf32.f32 " \
                 "{%0,%1,%2,%3},{%4,%5,%6,%7},{%8,%9},{%0,%1,%2,%3};" \
                 : "+f"((d)[0]), "+f"((d)[1]), "+f"((d)[2]), "+f"((d)[3]) \
                 : "r"(a0), "r"(a1), "r"(a2), "r"(a3), "r"(b0), "r"(b1))

#define MMA_F16(d, a0, a1, a2, a3, b0, b1) \
    asm volatile("mma.sync.aligned.m16n8k16.row.col.f32.f16.f16.f32 " \
                 "{%0,%1,%2,%3},{%4,%5,%6,%7},{%8,%9},{%0,%1,%2,%3};" \
                 : "+f"((d)[0]), "+f"((d)[1]), "+f"((d)[2]), "+f"((d)[3]) \
                 : "r"(a0), "r"(a1), "r"(a2), "r"(a3), "r"(b0), "r"(b1))

#define LDSM_X4T(r0, r1, r2, r3, addr) \
    asm volatile("ldmatrix.sync.aligned.m8n8.x4.trans.shared.b16 " \
                 "{%0,%1,%2,%3}, [%4];" \
                 : "=r"(r0), "=r"(r1), "=r"(r2), "=r"(r3) : "r"(addr))

__device__ __forceinline__ float ex2(float x) {
    float r;
    asm("ex2.approx.ftz.f32 %0, %1;" : "=f"(r) : "f"(x));
    return r;
}
__device__ __forceinline__ float trunct(float x) {       // tf32 truncation
    return __uint_as_float(__float_as_uint(x) & 0xFFFFE000u);
}
__device__ __forceinline__ uint32_t packh2(float hi, float lo) {
    uint32_t r;   // r = {lo half = cvt(lo), hi half = cvt(hi)}
    asm("cvt.rn.f16x2.f32 %0, %1, %2;" : "=r"(r) : "f"(hi), "f"(lo));
    return r;
}
__device__ __forceinline__ uint32_t smem_u32(const void* p) {
    uint32_t a;
    asm("{ .reg .u64 t; cvta.to.shared.u64 t, %1; cvt.u32.u64 %0, t; }" : "=r"(a) : "l"(p));
    return a;
}
#define F2U(x) __float_as_uint(x)

__device__ float g_opart[NSPLIT][N1v][DD];
__device__ float g_m[NSPLIT][N1v];
__device__ float g_l[NSPLIT][N1v];

__global__ __launch_bounds__(NTHREADS, 2)
void attn_fwd_kernel(const float* __restrict__ P1,
                     const float* __restrict__ P2)
{
    extern __shared__ char smem[];
    float*  sqh  = (float*)(smem + SQH_B);
    __half* sql  = (__half*)(smem + SQL_B);
    float*  khp  = (float*)(smem + KHP_B);   // K fragment-paired (d, d+4)
    __half* sv16 = (__half*)(smem + SV_B);   // V fp16, [k][d]
    __half* sp16 = (__half*)(smem + SP_B);   // P fp16, [row][kvcol]
    float*  pmax = (float*)(smem + PMX_B);
    float*  lh   = (float*)(smem + LH_B);

    const int t    = threadIdx.x;
    const int wid  = t >> 5, lane = t & 31;
    const int gid  = lane >> 2, tid = lane & 3;
    const int wr   = 16 * (wid & 3);        // m-block base (rows)
    const int ph   = wid >> 2;              // col-half id (0/1)
    const int wc   = 32 * ph;               // GEMM1 n-half base (S cols)
    const int wc2  = 64 * ph;               // GEMM2 n-half base (O cols)
    const int rA   = wr + gid, rB = rA + 8;

    // ldmatrix per-lane base (tile arrangement: m0=(k0..7,d0..7),
    // m1=(k8..15,d0..7), m2=(k0..7,d8..15), m3=(k8..15,d8..15))
    const uint32_t sv_u = smem_u32(sv16);
    const int krow_l = (lane & 7) + 8 * ((lane >> 3) & 1);
    const int dcol_l = 8 * (lane >> 4);
    const uint32_t ldsm_base = sv_u + (uint32_t)(krow_l * (VS * 2))
                             + (uint32_t)((dcol_l + wc2) * 2);

    for (int job = blockIdx.x; job < NJOBS; job += GRID) {
        const int qt    = job >> 3;
        const int s     = job & (NSPLIT - 1);
        const int qbase = qt * BM;
        const int kv0   = s * NKV_JOB;

        __syncthreads();   // previous job fully done with smem

        // ---- Q setup: raw-hi fragment-paired + fp16 lo (paired) ----
        {
            const float4* qsrc = (const float4*)(P1 + (size_t)qbase * DD);
            #pragma unroll
            for (int i = 0; i < 4; i++) {
                int cnk = t + i * NTHREADS;      // 0..1023 (8-float chunks)
                int row = cnk >> 4, ch = cnk & 15;
                float4 v0 = qsrc[row * 32 + ch * 2];
                float4 v1 = qsrc[row * 32 + ch * 2 + 1];
                float q[8] = {v0.x, v0.y, v0.z, v0.w, v1.x, v1.y, v1.z, v1.w};
                float2* dh = (float2*)&sqh[row * QHS + ch * 8];
                __half2* dl = (__half2*)&sql[row * QLS + ch * 8];
                #pragma unroll
                for (int j = 0; j < 4; j++) {
                    dh[j] = make_float2(q[j], q[j + 4]);   // (d, d+4) pair
                    dl[j] = __floats2half2_rn(q[j] - trunct(q[j]),
                                              q[j + 4] - trunct(q[j + 4]));
                }
            }
        }

        float m0 = -CUDART_INF_F, m1 = -CUDART_INF_F, l0 = 0.f, l1 = 0.f;
        float O[8][4];
        #pragma unroll
        for (int nb = 0; nb < 8; nb++)
            #pragma unroll
            for (int c = 0; c < 4; c++) O[nb][c] = 0.f;

        for (int it = 0; it < NT_JOB; it++) {
            // ---- KV tile load: K fragment-paired + V fp16 ----
            {
                const float4* src =
                    (const float4*)(P2 + (size_t)(kv0 + it * BN) * DD);
                #pragma unroll
                for (int i = 0; i < 4; i++) {
                    int cnk = t + i * NTHREADS;   // 0..1023
                    int row = cnk >> 4, ch = cnk & 15;
                    float4 v0 = src[row * 32 + ch * 2];
                    float4 v1 = src[row * 32 + ch * 2 + 1];
                    // K hi pairs (d, d+4)
                    float4* dk = (float4*)&khp[row * KPS + ch * 8];
                    dk[0] = make_float4(v0.x, v1.x, v0.y, v1.y);
                    dk[1] = make_float4(v0.z, v1.z, v0.w, v1.w);
                    // V fp16, natural [k][d] order
                    uint4 pv;
                    pv.x = packh2(v0.y, v0.x);
                    pv.y = packh2(v0.w, v0.z);
                    pv.z = packh2(v1.y, v1.x);
                    pv.w = packh2(v1.w, v1.z);
                    *(uint4*)&sv16[row * VS + ch * 8] = pv;
                }
            }
            __syncthreads();

            // ---- GEMM1 (tf32): S = qh*kh + qh*kl + ql*kh ----
            float D[4][4];
            #pragma unroll
            for (int nb = 0; nb < 4; nb++)
                #pragma unroll
                for (int c = 0; c < 4; c++) D[nb][c] = 0.f;

            #pragma unroll 4
            for (int ks = 0; ks < 16; ks++) {
                const int k0 = ks * 8;
                float2 qa = *(const float2*)&sqh[rA * QHS + k0 + 2 * tid];
                float2 qb = *(const float2*)&sqh[rB * QHS + k0 + 2 * tid];
                float2 ea = __half22float2(
                    *(const __half2*)&sql[rA * QLS + k0 + 2 * tid]);
                float2 eb = __half22float2(
                    *(const __half2*)&sql[rB * QLS + k0 + 2 * tid]);
                uint32_t a0 = F2U(qa.x), a2 = F2U(qa.y);
                uint32_t a1 = F2U(qb.x), a3 = F2U(qb.y);
                uint32_t e0 = F2U(ea.x), e2 = F2U(ea.y);
                uint32_t e1 = F2U(eb.x), e3 = F2U(eb.y);
                #pragma unroll
                for (int nb = 0; nb < 4; nb++) {
                    float2 bv = *(const float2*)
                        &khp[(wc + nb * 8 + gid) * KPS + k0 + 2 * tid];
                    uint32_t bh0 = F2U(bv.x), bh1 = F2U(bv.y);     // raw hi
                    uint32_t bl0 = F2U(bv.x - trunct(bv.x));       // lo
                    uint32_t bl1 = F2U(bv.y - trunct(bv.y));
                    MMA_TF32(D[nb], a0, a1, a2, a3, bh0, bh1);
                    MMA_TF32(D[nb], a0, a1, a2, a3, bl0, bl1);
                    MMA_TF32(D[nb], e0, e1, e2, e3, bh0, bh1);
                }
            }

            // ---- softmax (cross-half max via smem) ----
            float mx0 = fmaxf(fmaxf(D[0][0], D[0][1]), fmaxf(D[1][0], D[1][1]));
            mx0 = fmaxf(mx0, fmaxf(fmaxf(D[2][0], D[2][1]), fmaxf(D[3][0], D[3][1])));
            float mx1 = fmaxf(fmaxf(D[0][2], D[0][3]), fmaxf(D[1][2], D[1][3]));
            mx1 = fmaxf(mx1, fmaxf(fmaxf(D[2][2], D[2][3]), fmaxf(D[3][2], D[3][3])));
            mx0 *= C2F; mx1 *= C2F;
            #pragma unroll
            for (int off = 1; off < 4; off <<= 1) {
                mx0 = fmaxf(mx0, __shfl_xor_sync(0xffffffffu, mx0, off));
                mx1 = fmaxf(mx1, __shfl_xor_sync(0xffffffffu, mx1, off));
            }
            if (tid == 0) {
                pmax[ph * 64 + rA] = mx0;
                pmax[ph * 64 + rB] = mx1;
            }
            __syncthreads();
            float mn0 = fmaxf(m0, fmaxf(mx0, pmax[(1 - ph) * 64 + rA]));
            float mn1 = fmaxf(m1, fmaxf(mx1, pmax[(1 - ph) * 64 + rB]));
            float cr0 = ex2(m0 - mn0), cr1 = ex2(m1 - mn1);
            m0 = mn0; m1 = mn1;

            float ps0 = 0.f, ps1 = 0.f;
            #pragma unroll
            for (int nb = 0; nb < 4; nb++) {
                float p00 = ex2(fmaf(D[nb][0], C2F, -mn0));
                float p01 = ex2(fmaf(D[nb][1], C2F, -mn0));
                float p10 = ex2(fmaf(D[nb][2], C2F, -mn1));
                float p11 = ex2(fmaf(D[nb][3], C2F, -mn1));
                int cc = wc + nb * 8 + 2 * tid;
                uint32_t pa = packh2(p01, p00);   // {lo=p00, hi=p01}
                uint32_t pb = packh2(p11, p10);
                *(uint32_t*)&sp16[rA * PS + cc] = pa;
                *(uint32_t*)&sp16[rB * PS + cc] = pb;
                // l from the ROUNDED values (consistency with O)
                float2 fa = __half22float2(*(__half2*)&pa);
                float2 fb = __half22float2(*(__half2*)&pb);
                ps0 += fa.x + fa.y; ps1 += fb.x + fb.y;
            }
            l0 = fmaf(l0, cr0, ps0);
            l1 = fmaf(l1, cr1, ps1);
            __syncthreads();   // sp16 visible to all warps

            // ---- O *= corr ----
            #pragma unroll
            for (int nb = 0; nb < 8; nb++) {
                O[nb][0] *= cr0; O[nb][1] *= cr0;
                O[nb][2] *= cr1; O[nb][3] *= cr1;
            }

            // ---- GEMM2 (f16 MMA): O += P16 @ V16, B via ldmatrix.trans ----
            #pragma unroll
            for (int ks = 0; ks < 4; ks++) {
                const int k16 = ks * 16;
                uint32_t a0 = *(const uint32_t*)&sp16[rA * PS + k16 + 2 * tid];
                uint32_t a1 = *(const uint32_t*)&sp16[rB * PS + k16 + 2 * tid];
                uint32_t a2 = *(const uint32_t*)&sp16[rA * PS + k16 + 8 + 2 * tid];
                uint32_t a3 = *(const uint32_t*)&sp16[rB * PS + k16 + 8 + 2 * tid];
                #pragma unroll
                for (int p = 0; p < 4; p++) {
                    uint32_t b0, b1, b2, b3;
                    LDSM_X4T(b0, b1, b2, b3,
                             ldsm_base + (uint32_t)(k16 * (VS * 2) + p * 32));
                    MMA_F16(O[2 * p],     a0, a1, a2, a3, b0, b1);
                    MMA_F16(O[2 * p + 1], a0, a1, a2, a3, b2, b3);
                }
            }
            __syncthreads();   // smem reads done before next tile load
        }

        // ---- finalize l ----
        #pragma unroll
        for (int off = 1; off < 4; off <<= 1) {
            l0 += __shfl_xor_sync(0xffffffffu, l0, off);
            l1 += __shfl_xor_sync(0xffffffffu, l1, off);
        }
        if (tid == 0) {
            lh[ph * 64 + rA] = l0;
            lh[ph * 64 + rB] = l1;
        }
        __syncthreads();
        float L0 = lh[rA] + lh[64 + rA];
        float L1 = lh[rB] + lh[64 + rB];
        float inv0 = 1.0f / L0, inv1 = 1.0f / L1;
        if (ph == 0 && tid == 0) {
            g_m[s][qbase + rA] = m0; g_l[s][qbase + rA] = L0;
            g_m[s][qbase + rB] = m1; g_l[s][qbase + rB] = L1;
        }

        // ---- epilogue: normalized partial O ----
        {
            float* dstA = &g_opart[s][qbase + rA][wc2 + 2 * tid];
            float* dstB = &g_opart[s][qbase + rB][wc2 + 2 * tid];
            #pragma unroll
            for (int nb = 0; nb < 8; nb++) {
                *(float2*)(dstA + nb * 8) =
                    make_float2(O[nb][0] * inv0, O[nb][1] * inv0);
                *(float2*)(dstB + nb * 8) =
                    make_float2(O[nb][2] * inv1, O[nb][3] * inv1);
            }
        }
    }
}

// combine the NSPLIT KV splits
__global__ void merge_kernel(float* __restrict__ out)
{
    int idx = blockIdx.x * blockDim.x + threadIdx.x;
    int row = idx >> 7;
    int col = idx & (DD - 1);
    float m[NSPLIT];
    float M = -CUDART_INF_F;
    #pragma unroll
    for (int s = 0; s < NSPLIT; s++) { m[s] = g_m[s][row]; M = fmaxf(M, m[s]); }
    float wsum = 0.f, acc = 0.f;
    #pragma unroll
    for (int s = 0; s < NSPLIT; s++) {
        float w = g_l[s][row] * exp2f(m[s] - M);
        acc  = fmaf(w, g_opart[s][row][col], acc);
        wsum += w;
    }
    out[idx] = acc / wsum;
}

extern "C" void kernel_launch(void* const* d_in, const int* in_sizes, int n_in,
                              void* d_out, int out_size)
{
    const float* p1 = (const float*)d_in[0];
    const float* p2 = (const float*)d_in[1];
    float* out = (float*)d_out;

    cudaFuncSetAttribute(attn_fwd_kernel,
                         cudaFuncAttributeMaxDynamicSharedMemorySize, SMEM_B);
    attn_fwd_kernel<<<GRID, NTHREADS, SMEM_B>>>(p1, p2);
    merge_kernel<<<(N1v * DD) / 256, 256>>>(out);
}

// round 17
// speedup vs baseline: 3.8430x; 1.6463x over previous
#include <cuda_runtime.h>
#include <math_constants.h>
#include <cuda_fp16.h>
#include <cstdint>

// out = softmax(p1 @ p2^T * sqrt(N2)) @ p2 ; N1=N2=8192, D=128, fp32.
//
// Round 17: GEMM1 -> fp16 m16n8k16 MMA, 4-term split (qh+ql)(kh+kl), all
// operands ldmatrix-fed. Captures the exact fp32 product to ~2^-23 (better
// than R16's tf32 truncation split). kh16 doubles as the fp16 V for GEMM2
// (same [kv][d] layout) -> separate V array deleted. GEMM2 A-frags also via
// ldmatrix. Softmax / split-KV x8 / grid 296 / merge kernel unchanged.

#define N1v 8192
#define N2v 8192
#define DD  128
#define BM  64
#define BN  64
#define NSPLIT 8
#define NKV_JOB (N2v / NSPLIT)
#define NT_JOB  (NKV_JOB / BN)         // 16
#define NJOBS   ((N1v / BM) * NSPLIT)  // 1024
#define GRID    296
#define QS 136                         // qh/ql row stride (halves)
#define KS 136                         // kh/kl row stride (halves)
#define PS 72                          // sp16 row stride (halves)
#define NTHREADS 256
#define C2F 130.57784f                 // sqrt(8192) * log2(e)

// smem layout (bytes)
#define QH_B 0
#define QL_B (QH_B + BM * QS * 2)      // 17408
#define KH_B (QL_B + BM * QS * 2)      // 34816
#define KL_B (KH_B + BN * KS * 2)      // 52224
#define SP_B (KL_B + BN * KS * 2)      // 69632
#define PMX_B (SP_B + BM * PS * 2)     // 78848
#define LH_B  (PMX_B + 512)            // 79360
#define SMEM_B (LH_B + 512)            // 79872

#define MMA_F16(d, a0, a1, a2, a3, b0, b1) \
    asm volatile("mma.sync.aligned.m16n8k16.row.col.f32.f16.f16.f32 " \
                 "{%0,%1,%2,%3},{%4,%5,%6,%7},{%8,%9},{%0,%1,%2,%3};" \
                 : "+f"((d)[0]), "+f"((d)[1]), "+f"((d)[2]), "+f"((d)[3]) \
                 : "r"(a0), "r"(a1), "r"(a2), "r"(a3), "r"(b0), "r"(b1))

#define LDSM_X4(r0, r1, r2, r3, addr) \
    asm volatile("ldmatrix.sync.aligned.m8n8.x4.shared.b16 " \
                 "{%0,%1,%2,%3}, [%4];" \
                 : "=r"(r0), "=r"(r1), "=r"(r2), "=r"(r3) : "r"(addr))

#define LDSM_X4T(r0, r1, r2, r3, addr) \
    asm volatile("ldmatrix.sync.aligned.m8n8.x4.trans.shared.b16 " \
                 "{%0,%1,%2,%3}, [%4];" \
                 : "=r"(r0), "=r"(r1), "=r"(r2), "=r"(r3) : "r"(addr))

__device__ __forceinline__ float ex2(float x) {
    float r;
    asm("ex2.approx.ftz.f32 %0, %1;" : "=f"(r) : "f"(x));
    return r;
}
__device__ __forceinline__ uint32_t packh2(float hi, float lo) {
    uint32_t r;   // {lo half, hi half}
    asm("cvt.rn.f16x2.f32 %0, %1, %2;" : "=r"(r) : "f"(hi), "f"(lo));
    return r;
}
__device__ __forceinline__ uint32_t smem_u32(const void* p) {
    uint32_t a;
    asm("{ .reg .u64 t; cvta.to.shared.u64 t, %1; cvt.u32.u64 %0, t; }" : "=r"(a) : "l"(p));
    return a;
}

// split 8 floats into fp16 hi + fp16 lo (exact to ~2^-23 combined)
__device__ __forceinline__ void split8(const float4 v0, const float4 v1,
                                       uint4* ph, uint4* pl) {
    float q[8] = {v0.x, v0.y, v0.z, v0.w, v1.x, v1.y, v1.z, v1.w};
    uint32_t* hp = (uint32_t*)ph;
    uint32_t* lp = (uint32_t*)pl;
    #pragma unroll
    for (int j = 0; j < 4; j++) {
        uint32_t h = packh2(q[2 * j + 1], q[2 * j]);
        hp[j] = h;
        float2 hf = __half22float2(*(__half2*)&h);
        lp[j] = packh2(q[2 * j + 1] - hf.y, q[2 * j] - hf.x);
    }
}

__device__ float g_opart[NSPLIT][N1v][DD];
__device__ float g_m[NSPLIT][N1v];
__device__ float g_l[NSPLIT][N1v];

__global__ __launch_bounds__(NTHREADS, 2)
void attn_fwd_kernel(const float* __restrict__ P1,
                     const float* __restrict__ P2)
{
    extern __shared__ char smem[];
    __half* qh16 = (__half*)(smem + QH_B);
    __half* ql16 = (__half*)(smem + QL_B);
    __half* kh16 = (__half*)(smem + KH_B);   // also the fp16 V for GEMM2
    __half* kl16 = (__half*)(smem + KL_B);
    __half* sp16 = (__half*)(smem + SP_B);
    float*  pmax = (float*)(smem + PMX_B);
    float*  lh   = (float*)(smem + LH_B);

    const int t    = threadIdx.x;
    const int wid  = t >> 5, lane = t & 31;
    const int gid  = lane >> 2, tid = lane & 3;
    const int wr   = 16 * (wid & 3);        // m-block base (rows)
    const int ph   = wid >> 2;              // col-half id (0/1)
    const int wc   = 32 * ph;               // GEMM1 n-half base (S cols)
    const int wc2  = 64 * ph;               // GEMM2 n-half base (O cols)
    const int rA   = wr + gid, rB = rA + 8;

    const uint32_t qh_u = smem_u32(qh16), ql_u = smem_u32(ql16);
    const uint32_t kh_u = smem_u32(kh16), kl_u = smem_u32(kl16);
    const uint32_t sp_u = smem_u32(sp16);

    // GEMM1 A ldmatrix address part: lane&15 -> row, lane>>4 -> k half
    const uint32_t aoff = (uint32_t)((wr + (lane & 15)) * QS * 2 + (lane >> 4) * 16);
    // GEMM1 B ldmatrix address part: n row + k half
    const uint32_t boff = (uint32_t)(
        (wc + (lane & 7) + 8 * (lane >> 4)) * KS * 2 + ((lane >> 3) & 1) * 16);
    // GEMM2 A (P) ldmatrix address part
    const uint32_t poff = (uint32_t)((wr + (lane & 15)) * PS * 2 + (lane >> 4) * 16);
    // GEMM2 B (V = kh16) trans-ldmatrix address part
    const uint32_t voff = (uint32_t)(
        ((lane & 7) + 8 * ((lane >> 3) & 1)) * KS * 2 + (8 * (lane >> 4) + wc2) * 2);

    for (int job = blockIdx.x; job < NJOBS; job += GRID) {
        const int qt    = job >> 3;
        const int s     = job & (NSPLIT - 1);
        const int qbase = qt * BM;
        const int kv0   = s * NKV_JOB;

        __syncthreads();   // previous job fully done with smem

        // ---- Q setup: fp16 hi/lo split ----
        {
            const float4* qsrc = (const float4*)(P1 + (size_t)qbase * DD);
            #pragma unroll
            for (int i = 0; i < 4; i++) {
                int cnk = t + i * NTHREADS;      // 0..1023
                int row = cnk >> 4, ch = cnk & 15;
                uint4 hh, ll;
                split8(qsrc[row * 32 + ch * 2], qsrc[row * 32 + ch * 2 + 1], &hh, &ll);
                *(uint4*)&qh16[row * QS + ch * 8] = hh;
                *(uint4*)&ql16[row * QS + ch * 8] = ll;
            }
        }

        float m0 = -CUDART_INF_F, m1 = -CUDART_INF_F, l0 = 0.f, l1 = 0.f;
        float O[8][4];
        #pragma unroll
        for (int nb = 0; nb < 8; nb++)
            #pragma unroll
            for (int c = 0; c < 4; c++) O[nb][c] = 0.f;

        for (int it = 0; it < NT_JOB; it++) {
            // ---- KV tile load: fp16 hi/lo split (kh16 doubles as V) ----
            {
                const float4* src =
                    (const float4*)(P2 + (size_t)(kv0 + it * BN) * DD);
                #pragma unroll
                for (int i = 0; i < 4; i++) {
                    int cnk = t + i * NTHREADS;
                    int row = cnk >> 4, ch = cnk & 15;
                    uint4 hh, ll;
                    split8(src[row * 32 + ch * 2], src[row * 32 + ch * 2 + 1], &hh, &ll);
                    *(uint4*)&kh16[row * KS + ch * 8] = hh;
                    *(uint4*)&kl16[row * KS + ch * 8] = ll;
                }
            }
            __syncthreads();

            // ---- GEMM1 (f16 MMA): S = (qh+ql).(kh+kl) ----
            float D[4][4];
            #pragma unroll
            for (int nb = 0; nb < 4; nb++)
                #pragma unroll
                for (int c = 0; c < 4; c++) D[nb][c] = 0.f;

            #pragma unroll
            for (int ks = 0; ks < 8; ks++) {
                const uint32_t ko = (uint32_t)(ks * 32);
                uint32_t ah0, ah1, ah2, ah3, al0, al1, al2, al3;
                LDSM_X4(ah0, ah1, ah2, ah3, qh_u + aoff + ko);
                LDSM_X4(al0, al1, al2, al3, ql_u + aoff + ko);
                #pragma unroll
                for (int p = 0; p < 2; p++) {
                    const uint32_t bo = boff + (uint32_t)(p * 16 * KS * 2) + ko;
                    uint32_t bh0, bh1, bh2, bh3, bl0, bl1, bl2, bl3;
                    LDSM_X4(bh0, bh1, bh2, bh3, kh_u + bo);
                    LDSM_X4(bl0, bl1, bl2, bl3, kl_u + bo);
                    MMA_F16(D[2 * p],     ah0, ah1, ah2, ah3, bh0, bh1);
                    MMA_F16(D[2 * p],     ah0, ah1, ah2, ah3, bl0, bl1);
                    MMA_F16(D[2 * p],     al0, al1, al2, al3, bh0, bh1);
                    MMA_F16(D[2 * p],     al0, al1, al2, al3, bl0, bl1);
                    MMA_F16(D[2 * p + 1], ah0, ah1, ah2, ah3, bh2, bh3);
                    MMA_F16(D[2 * p + 1], ah0, ah1, ah2, ah3, bl2, bl3);
                    MMA_F16(D[2 * p + 1], al0, al1, al2, al3, bh2, bh3);
                    MMA_F16(D[2 * p + 1], al0, al1, al2, al3, bl2, bl3);
                }
            }

            // ---- softmax (cross-half max via smem) ----
            float mx0 = fmaxf(fmaxf(D[0][0], D[0][1]), fmaxf(D[1][0], D[1][1]));
            mx0 = fmaxf(mx0, fmaxf(fmaxf(D[2][0], D[2][1]), fmaxf(D[3][0], D[3][1])));
            float mx1 = fmaxf(fmaxf(D[0][2], D[0][3]), fmaxf(D[1][2], D[1][3]));
            mx1 = fmaxf(mx1, fmaxf(fmaxf(D[2][2], D[2][3]), fmaxf(D[3][2], D[3][3])));
            mx0 *= C2F; mx1 *= C2F;
            #pragma unroll
            for (int off = 1; off < 4; off <<= 1) {
                mx0 = fmaxf(mx0, __shfl_xor_sync(0xffffffffu, mx0, off));
                mx1 = fmaxf(mx1, __shfl_xor_sync(0xffffffffu, mx1, off));
            }
            if (tid == 0) {
                pmax[ph * 64 + rA] = mx0;
                pmax[ph * 64 + rB] = mx1;
            }
            __syncthreads();
            float mn0 = fmaxf(m0, fmaxf(mx0, pmax[(1 - ph) * 64 + rA]));
            float mn1 = fmaxf(m1, fmaxf(mx1, pmax[(1 - ph) * 64 + rB]));
            float cr0 = ex2(m0 - mn0), cr1 = ex2(m1 - mn1);
            m0 = mn0; m1 = mn1;

            float ps0 = 0.f, ps1 = 0.f;
            #pragma unroll
            for (int nb = 0; nb < 4; nb++) {
                float p00 = ex2(fmaf(D[nb][0], C2F, -mn0));
                float p01 = ex2(fmaf(D[nb][1], C2F, -mn0));
                float p10 = ex2(fmaf(D[nb][2], C2F, -mn1));
                float p11 = ex2(fmaf(D[nb][3], C2F, -mn1));
                int cc = wc + nb * 8 + 2 * tid;
                uint32_t pa = packh2(p01, p00);
                uint32_t pb = packh2(p11, p10);
                *(uint32_t*)&sp16[rA * PS + cc] = pa;
                *(uint32_t*)&sp16[rB * PS + cc] = pb;
                // l from ROUNDED values (consistency with O)
                float2 fa = __half22float2(*(__half2*)&pa);
                float2 fb = __half22float2(*(__half2*)&pb);
                ps0 += fa.x + fa.y; ps1 += fb.x + fb.y;
            }
            l0 = fmaf(l0, cr0, ps0);
            l1 = fmaf(l1, cr1, ps1);
            __syncthreads();   // sp16 visible

            // ---- O *= corr ----
            #pragma unroll
            for (int nb = 0; nb < 8; nb++) {
                O[nb][0] *= cr0; O[nb][1] *= cr0;
                O[nb][2] *= cr1; O[nb][3] *= cr1;
            }

            // ---- GEMM2 (f16 MMA): O += P16 @ V16 (V = kh16) ----
            #pragma unroll
            for (int ks = 0; ks < 4; ks++) {
                const uint32_t k16 = (uint32_t)(ks * 16);
                uint32_t a0, a1, a2, a3;
                LDSM_X4(a0, a1, a2, a3, sp_u + poff + (uint32_t)(ks * 32));
                #pragma unroll
                for (int p = 0; p < 4; p++) {
                    uint32_t b0, b1, b2, b3;
                    LDSM_X4T(b0, b1, b2, b3,
                             kh_u + voff + k16 * (KS * 2) + (uint32_t)(p * 32));
                    MMA_F16(O[2 * p],     a0, a1, a2, a3, b0, b1);
                    MMA_F16(O[2 * p + 1], a0, a1, a2, a3, b2, b3);
                }
            }
            __syncthreads();   // smem reads done before next tile load
        }

        // ---- finalize l ----
        #pragma unroll
        for (int off = 1; off < 4; off <<= 1) {
            l0 += __shfl_xor_sync(0xffffffffu, l0, off);
            l1 += __shfl_xor_sync(0xffffffffu, l1, off);
        }
        if (tid == 0) {
            lh[ph * 64 + rA] = l0;
            lh[ph * 64 + rB] = l1;
        }
        __syncthreads();
        float L0 = lh[rA] + lh[64 + rA];
        float L1 = lh[rB] + lh[64 + rB];
        float inv0 = 1.0f / L0, inv1 = 1.0f / L1;
        if (ph == 0 && tid == 0) {
            g_m[s][qbase + rA] = m0; g_l[s][qbase + rA] = L0;
            g_m[s][qbase + rB] = m1; g_l[s][qbase + rB] = L1;
        }

        // ---- epilogue: normalized partial O ----
        {
            float* dstA = &g_opart[s][qbase + rA][wc2 + 2 * tid];
            float* dstB = &g_opart[s][qbase + rB][wc2 + 2 * tid];
            #pragma unroll
            for (int nb = 0; nb < 8; nb++) {
                *(float2*)(dstA + nb * 8) =
                    make_float2(O[nb][0] * inv0, O[nb][1] * inv0);
                *(float2*)(dstB + nb * 8) =
                    make_float2(O[nb][2] * inv1, O[nb][3] * inv1);
            }
        }
    }
}

// combine the NSPLIT KV splits
__global__ void merge_kernel(float* __restrict__ out)
{
    int idx = blockIdx.x * blockDim.x + threadIdx.x;
    int row = idx >> 7;
    int col = idx & (DD - 1);
    float m[NSPLIT];
    float M = -CUDART_INF_F;
    #pragma unroll
    for (int s = 0; s < NSPLIT; s++) { m[s] = g_m[s][row]; M = fmaxf(M, m[s]); }
    float wsum = 0.f, acc = 0.f;
    #pragma unroll
    for (int s = 0; s < NSPLIT; s++) {
        float w = g_l[s][row] * exp2f(m[s] - M);
        acc  = fmaf(w, g_opart[s][row][col], acc);
        wsum += w;
    }
    out[idx] = acc / wsum;
}

extern "C" void kernel_launch(void* const* d_in, const int* in_sizes, int n_in,
                              void* d_out, int out_size)
{
    const float* p1 = (const float*)d_in[0];
    const float* p2 = (const float*)d_in[1];
    float* out = (float*)d_out;

    cudaFuncSetAttribute(attn_fwd_kernel,
                         cudaFuncAttributeMaxDynamicSharedMemorySize, SMEM_B);
    attn_fwd_kernel<<<GRID, NTHREADS, SMEM_B>>>(p1, p2);
    merge_kernel<<<(N1v * DD) / 256, 256>>>(out);
}